// round 6
// baseline (speedup 1.0000x reference)
#include <cuda_runtime.h>
#include <math.h>

#define TPB 256
#define NBATCH 16
#define NBOX 64
#define NCLS 30

// softplus blocks: each handles 512 float4 (2048 floats)
#define SP0_BLOCKS 50
#define SP1_BLOCKS 13
#define SP2_BLOCKS 4
#define SP_BLOCKS (SP0_BLOCKS + SP1_BLOCKS + SP2_BLOCKS)   // 67
#define AS_BLOCKS 96                                        // 3 scales * 16 batches * 2 halves
#define TOTAL_BLOCKS (SP_BLOCKS + AS_BLOCKS)                // 163

__device__ float  g_blk_sp[SP_BLOCKS];
__device__ float4 g_blk_as[AS_BLOCKS];     // {cls_sum, reg_sum, obj_pos_sum, npos}
__device__ unsigned int g_done = 0;

static __device__ __forceinline__ float softplus_f(float x) {
    return fmaxf(x, 0.0f) + __logf(1.0f + __expf(-fabsf(x)));
}

// block reduce; result valid on thread 0
static __device__ __forceinline__ float blk_reduce(float v) {
    __shared__ float sh[TPB / 32];
    __syncthreads();
    #pragma unroll
    for (int o = 16; o > 0; o >>= 1) v += __shfl_down_sync(0xffffffffu, v, o);
    int lane = threadIdx.x & 31, w = threadIdx.x >> 5;
    if (lane == 0) sh[w] = v;
    __syncthreads();
    v = (threadIdx.x < TPB / 32) ? sh[threadIdx.x] : 0.0f;
    if (w == 0) {
        #pragma unroll
        for (int o = TPB / 64; o > 0; o >>= 1) v += __shfl_down_sync(0xffffffffu, v, o);
    }
    return v;
}

// fused 4-value block reduce (2 barriers); results valid on thread 0 in r[0..3]
static __device__ __forceinline__ void blk_reduce4(float v0, float v1, float v2, float v3,
                                                   float* r) {
    __shared__ float sh[TPB / 32][4];
    __syncthreads();
    #pragma unroll
    for (int o = 16; o > 0; o >>= 1) {
        v0 += __shfl_xor_sync(0xffffffffu, v0, o);
        v1 += __shfl_xor_sync(0xffffffffu, v1, o);
        v2 += __shfl_xor_sync(0xffffffffu, v2, o);
        v3 += __shfl_xor_sync(0xffffffffu, v3, o);
    }
    int lane = threadIdx.x & 31, w = threadIdx.x >> 5;
    if (lane == 0) { sh[w][0] = v0; sh[w][1] = v1; sh[w][2] = v2; sh[w][3] = v3; }
    __syncthreads();
    if (threadIdx.x == 0) {
        float a = 0.f, b = 0.f, c = 0.f, d = 0.f;
        #pragma unroll
        for (int i = 0; i < TPB / 32; i++) {
            a += sh[i][0]; b += sh[i][1]; c += sh[i][2]; d += sh[i][3];
        }
        r[0] = a; r[1] = b; r[2] = c; r[3] = d;
    }
}

__global__ __launch_bounds__(TPB)
void detloss_kernel(const float* __restrict__ cls0, const float* __restrict__ cls1,
                    const float* __restrict__ cls2,
                    const float* __restrict__ reg0, const float* __restrict__ reg1,
                    const float* __restrict__ reg2,
                    const float* __restrict__ obj0, const float* __restrict__ obj1,
                    const float* __restrict__ obj2,
                    const float* __restrict__ boxes, const int* __restrict__ labels,
                    float* __restrict__ out)
{
    const float* clsp[3] = {cls0, cls1, cls2};
    const float* regp[3] = {reg0, reg1, reg2};
    const float* objp[3] = {obj0, obj1, obj2};

    int bid = blockIdx.x;
    int t = threadIdx.x;

    if (bid < SP_BLOCKS) {
        // ---- objectness softplus sum: 2 float4 per thread ----
        const float4* src;
        int base, lim;
        if (bid < SP0_BLOCKS) {
            src = (const float4*)obj0; base = bid * 512; lim = 25600;
        } else if (bid < SP0_BLOCKS + SP1_BLOCKS) {
            src = (const float4*)obj1; base = (bid - SP0_BLOCKS) * 512; lim = 6400;
        } else {
            src = (const float4*)obj2; base = (bid - SP0_BLOCKS - SP1_BLOCKS) * 512; lim = 1600;
        }
        int i0 = base + t, i1 = base + 256 + t;
        float acc = 0.0f;
        if (i0 < lim) {
            float4 v = src[i0];
            acc += softplus_f(v.x) + softplus_f(v.y) + softplus_f(v.z) + softplus_f(v.w);
        }
        if (i1 < lim) {
            float4 v = src[i1];
            acc += softplus_f(v.x) + softplus_f(v.y) + softplus_f(v.z) + softplus_f(v.w);
        }
        float tot = blk_reduce(acc);
        if (t == 0) __stcg(&g_blk_sp[bid], tot);
    } else {
        // ---- per (scale, batch, half): 8 threads per box, 32 boxes per block ----
        int idx = bid - SP_BLOCKS;
        int s    = idx >> 5;        // 0..2
        int bh   = idx & 31;
        int b    = bh >> 1;         // 0..15
        int half = bh & 1;          // 0..1
        int Wd = 80 >> s;           // 80, 40, 20
        int HW = Wd * Wd;

        int box  = half * 32 + (t >> 3);   // global box id 0..63
        int part = t & 7;                  // 0..7

        __shared__ int spk[NBOX];   // packed (cell<<5)|label for ALL 64 boxes

        // threads 0..63 build the full collision table
        if (t < NBOX) {
            const float4 ab = ((const float4*)boxes)[b * NBOX + t];
            int agx = (int)(ab.x * (float)Wd);
            int agy = (int)(ab.y * (float)Wd);
            agx = max(0, min(agx, Wd - 1));
            agy = max(0, min(agy, Wd - 1));
            spk[t] = ((agy * Wd + agx) << 5) | labels[b * NBOX + t];
        }

        // own box: cell computed locally (pre-barrier) to issue gathers early
        const float4 bx = ((const float4*)boxes)[b * NBOX + box];
        int gx = (int)(bx.x * (float)Wd);
        int gy = (int)(bx.y * (float)Wd);
        gx = max(0, min(gx, Wd - 1));
        gy = max(0, min(gy, Wd - 1));
        int cell = gy * Wd + gx;

        // ---- speculative gathers: part p covers classes [4p, 4p+4) ----
        int cbase = part * 4;
        const float* cp = clsp[s] + (size_t)b * NCLS * HW + cell;
        float v[4];
        #pragma unroll
        for (int i = 0; i < 4; i++) {
            int c = cbase + i;
            int cc = min(c, NCLS - 1);
            float val = __ldg(&cp[(size_t)cc * HW]);
            v[i] = (c < NCLS) ? val : -1e30f;
        }
        // reg: parts 0-3 load coordinate p; obj: part 7 loads it
        float regv = (part < 4) ? __ldg(&regp[s][(size_t)b * 4 * HW + (size_t)part * HW + cell]) : 0.0f;
        float objv = (part == 7) ? __ldg(&objp[s][(size_t)b * HW + cell]) : 0.0f;
        __syncthreads();

        // ---- collision resolution: fully unrolled, branchless ----
        int mypk = spk[box];
        int mlpk = mypk;
        int lose = 0;
        #pragma unroll
        for (int j = 0; j < NBOX; j++) {
            int pj = spk[j];
            bool eq = (((pj ^ mypk) & ~31) == 0);    // same cell
            mlpk = (eq && pj < mlpk) ? pj : mlpk;     // min label among same-cell boxes
            lose |= (eq && j > box) ? 1 : 0;          // a later box overwrites this cell
        }
        int ml = mlpk & 31;
        bool winner = (lose == 0);

        // ---- group-of-8 combine (contiguous lanes, same warp) ----
        float m = fmaxf(fmaxf(v[0], v[1]), fmaxf(v[2], v[3]));
        m = fmaxf(m, __shfl_xor_sync(0xffffffffu, m, 1));
        m = fmaxf(m, __shfl_xor_sync(0xffffffffu, m, 2));
        m = fmaxf(m, __shfl_xor_sync(0xffffffffu, m, 4));

        float ssum = 0.0f, tgt = 0.0f;
        #pragma unroll
        for (int i = 0; i < 4; i++) {
            int c = cbase + i;
            ssum += __expf(v[i] - m);                 // padded entries -> exp(-huge)=0
            tgt = (c == ml) ? v[i] : tgt;
        }
        float bc = (part == 0) ? bx.x : (part == 1) ? bx.y : (part == 2) ? bx.z : bx.w;
        float sl = 0.0f;
        if (part < 4) {
            float d = fabsf(regv - bc);
            sl = (d < 1.0f) ? 0.5f * d * d : d - 0.5f;
        }

        ssum += __shfl_xor_sync(0xffffffffu, ssum, 1);
        ssum += __shfl_xor_sync(0xffffffffu, ssum, 2);
        ssum += __shfl_xor_sync(0xffffffffu, ssum, 4);
        tgt  += __shfl_xor_sync(0xffffffffu, tgt, 1);
        tgt  += __shfl_xor_sync(0xffffffffu, tgt, 2);
        tgt  += __shfl_xor_sync(0xffffffffu, tgt, 4);
        sl   += __shfl_xor_sync(0xffffffffu, sl, 1);
        sl   += __shfl_xor_sync(0xffffffffu, sl, 2);
        sl   += __shfl_xor_sync(0xffffffffu, sl, 4);

        float cls_l = 0.0f, reg_l = 0.0f, objp_l = 0.0f, np_l = 0.0f;
        if (winner) {
            if (part == 0) {
                np_l  = 1.0f;
                cls_l = m + __logf(ssum) - tgt;
                reg_l = fminf(sl * 0.25f, 10.0f);
            }
            if (part == 7) objp_l = objv;
        }
        __shared__ float res[4];
        blk_reduce4(cls_l, reg_l, objp_l, np_l, res);
        if (t == 0) {
            float4 o4 = make_float4(res[0], res[1], res[2], res[3]);
            __stcg(&g_blk_as[idx], o4);
        }
    }

    // ---- last arriving block: deterministic final reduce ----
    __shared__ bool amLast;
    if (t == 0) {
        __threadfence();   // order this block's partial store before the ticket
        unsigned vv = atomicAdd(&g_done, 1u);
        amLast = (vv == (unsigned)(gridDim.x - 1));
        if (amLast) __threadfence();   // acquire: see all other blocks' partials
    }
    __syncthreads();
    if (!amLast) return;

    // softplus partials: one load per thread, fused 3-way reduce
    float l0 = 0.f, l1 = 0.f, l2 = 0.f;
    if (t < SP_BLOCKS) {
        float pv = __ldcg(&g_blk_sp[t]);
        if (t < SP0_BLOCKS) l0 = pv;
        else if (t < SP0_BLOCKS + SP1_BLOCKS) l1 = pv;
        else l2 = pv;
    }
    __shared__ float spr[4];
    blk_reduce4(l0, l1, l2, 0.0f, spr);

    // assignment partials: thread-parallel, 3 masked passes (one per scale)
    float4 a4 = make_float4(0.f, 0.f, 0.f, 0.f);
    if (t < AS_BLOCKS) a4 = __ldcg(&g_blk_as[t]);
    int myscale = t >> 5;
    __shared__ float asr[3][4];
    #pragma unroll
    for (int s = 0; s < 3; s++) {
        bool on = (t < AS_BLOCKS) && (myscale == s);
        __shared__ float tmp[4];
        blk_reduce4(on ? a4.x : 0.f, on ? a4.y : 0.f, on ? a4.z : 0.f, on ? a4.w : 0.f, tmp);
        if (t == 0) { asr[s][0] = tmp[0]; asr[s][1] = tmp[1]; asr[s][2] = tmp[2]; asr[s][3] = tmp[3]; }
    }

    if (t == 0) {
        float cls_tot = 0.0f, reg_tot = 0.0f, obj_tot = 0.0f;
        #pragma unroll
        for (int s = 0; s < 3; s++) {
            float npos = fmaxf(asr[s][3], 1.0f);
            int Wd = 80 >> s;
            float Ms = (float)(NBATCH * Wd * Wd);
            cls_tot += asr[s][0] / npos;               // CLS_W = 1
            reg_tot += asr[s][1] / npos * 5.0f;        // REG_W = 5
            obj_tot += (spr[s] - asr[s][2]) / Ms;      // OBJ_W = 1
        }
        cls_tot *= (1.0f / 3.0f);
        reg_tot *= (1.0f / 3.0f);
        obj_tot *= (1.0f / 3.0f);
        out[0] = cls_tot + reg_tot + obj_tot;
        out[1] = cls_tot;
        out[2] = reg_tot;
        out[3] = obj_tot;
        g_done = 0;   // reset for next graph replay
    }
}

extern "C" void kernel_launch(void* const* d_in, const int* in_sizes, int n_in,
                              void* d_out, int out_size)
{
    const float *cls[3], *reg[3], *obj[3];
    if (in_sizes[1] == 409600) {   // dict order: cls0,reg0,obj0,cls1,...
        cls[0] = (const float*)d_in[0]; reg[0] = (const float*)d_in[1]; obj[0] = (const float*)d_in[2];
        cls[1] = (const float*)d_in[3]; reg[1] = (const float*)d_in[4]; obj[1] = (const float*)d_in[5];
        cls[2] = (const float*)d_in[6]; reg[2] = (const float*)d_in[7]; obj[2] = (const float*)d_in[8];
    } else {                        // signature order: cls0,cls1,cls2,reg0,...
        cls[0] = (const float*)d_in[0]; cls[1] = (const float*)d_in[1]; cls[2] = (const float*)d_in[2];
        reg[0] = (const float*)d_in[3]; reg[1] = (const float*)d_in[4]; reg[2] = (const float*)d_in[5];
        obj[0] = (const float*)d_in[6]; obj[1] = (const float*)d_in[7]; obj[2] = (const float*)d_in[8];
    }
    const float* boxes  = (const float*)d_in[9];
    const int*   labels = (const int*)d_in[10];
    float* out = (float*)d_out;

    detloss_kernel<<<TOTAL_BLOCKS, TPB>>>(
        cls[0], cls[1], cls[2],
        reg[0], reg[1], reg[2],
        obj[0], obj[1], obj[2],
        boxes, labels, out);
}

// round 7
// speedup vs baseline: 1.0029x; 1.0029x over previous
#include <cuda_runtime.h>
#include <math.h>

#define TPB 256
#define NBATCH 16
#define NBOX 64
#define NCLS 30

#define AS_BLOCKS 48                 // 3 scales * 16 batches; also carries softplus slices
// obj tensors as one virtual float4 array: 25600 + 6400 + 1600 = 33600 float4
#define SP_TOTAL_F4 33600
#define SP_PER_BLK 700               // 48 * 700 = 33600 exactly
#define SP_B01 25600                 // obj0/obj1 boundary (f4 units)
#define SP_B12 32000                 // obj1/obj2 boundary

__device__ float4 g_blk_as[AS_BLOCKS];   // {cls_sum, reg_sum, obj_pos_sum, npos}
__device__ float4 g_blk_sp[AS_BLOCKS];   // {sp0, sp1, sp2, unused}
__device__ unsigned int g_done = 0;

static __device__ __forceinline__ float softplus_f(float x) {
    return fmaxf(x, 0.0f) + __logf(1.0f + __expf(-fabsf(x)));
}
static __device__ __forceinline__ float sp4(float4 v) {
    return softplus_f(v.x) + softplus_f(v.y) + softplus_f(v.z) + softplus_f(v.w);
}

// fused 4-value block reduce (2 barriers); results valid on thread 0 in r[0..3]
static __device__ __forceinline__ void blk_reduce4(float v0, float v1, float v2, float v3,
                                                   float* r) {
    __shared__ float sh[TPB / 32][4];
    __syncthreads();
    #pragma unroll
    for (int o = 16; o > 0; o >>= 1) {
        v0 += __shfl_xor_sync(0xffffffffu, v0, o);
        v1 += __shfl_xor_sync(0xffffffffu, v1, o);
        v2 += __shfl_xor_sync(0xffffffffu, v2, o);
        v3 += __shfl_xor_sync(0xffffffffu, v3, o);
    }
    int lane = threadIdx.x & 31, w = threadIdx.x >> 5;
    if (lane == 0) { sh[w][0] = v0; sh[w][1] = v1; sh[w][2] = v2; sh[w][3] = v3; }
    __syncthreads();
    if (threadIdx.x == 0) {
        float a = 0.f, b = 0.f, c = 0.f, d = 0.f;
        #pragma unroll
        for (int i = 0; i < TPB / 32; i++) {
            a += sh[i][0]; b += sh[i][1]; c += sh[i][2]; d += sh[i][3];
        }
        r[0] = a; r[1] = b; r[2] = c; r[3] = d;
    }
}

__global__ __launch_bounds__(TPB)
void detloss_kernel(const float* __restrict__ cls0, const float* __restrict__ cls1,
                    const float* __restrict__ cls2,
                    const float* __restrict__ reg0, const float* __restrict__ reg1,
                    const float* __restrict__ reg2,
                    const float* __restrict__ obj0, const float* __restrict__ obj1,
                    const float* __restrict__ obj2,
                    const float* __restrict__ boxes, const int* __restrict__ labels,
                    float* __restrict__ out)
{
    const float* clsp[3] = {cls0, cls1, cls2};
    const float* regp[3] = {reg0, reg1, reg2};
    const float* objp[3] = {obj0, obj1, obj2};

    int idx = blockIdx.x;       // 0..47
    int t = threadIdx.x;
    int s = idx >> 4;           // 0..2
    int b = idx & 15;           // 0..15
    int Wd = 80 >> s;           // 80, 40, 20
    int HW = Wd * Wd;

    int box  = t >> 2;          // 0..63
    int part = t & 3;           // 0..3

    __shared__ int spk[NBOX];   // packed (cell<<5)|label

    // ---- box coords + cell (all 4 parts compute identically; broadcast loads) ----
    const float4 bx = ((const float4*)boxes)[b * NBOX + box];
    int gx = (int)(bx.x * (float)Wd);
    int gy = (int)(bx.y * (float)Wd);
    gx = max(0, min(gx, Wd - 1));
    gy = max(0, min(gy, Wd - 1));
    int cell = gy * Wd + gx;
    int lab  = labels[b * NBOX + box];
    int mypk = (cell << 5) | lab;
    if (part == 0) spk[box] = mypk;

    // ---- speculative gathers (issued before the barrier) ----
    int cbase = part * 8;
    const float* cp = clsp[s] + (size_t)b * NCLS * HW + cell;
    float v[8];
    #pragma unroll
    for (int i = 0; i < 8; i++) {
        int c = cbase + i;
        int cc = min(c, NCLS - 1);
        float val = __ldg(&cp[(size_t)cc * HW]);
        v[i] = (c < NCLS) ? val : -1e30f;
    }
    float regv = __ldg(&regp[s][(size_t)b * 4 * HW + (size_t)part * HW + cell]);
    float objv = (part == 3) ? __ldg(&objp[s][(size_t)b * HW + cell]) : 0.0f;

    // ---- softplus slice of the concatenated obj tensors (overlaps everything) ----
    int spbase = idx * SP_PER_BLK;
    float sp0 = 0.0f, sp1 = 0.0f, sp2 = 0.0f;
    #pragma unroll
    for (int k = 0; k < 3; k++) {
        int off = k * TPB + t;
        if (off < SP_PER_BLK) {
            int i = spbase + off;
            if (i < SP_B01) {
                sp0 += sp4(((const float4*)obj0)[i]);
            } else if (i < SP_B12) {
                sp1 += sp4(((const float4*)obj1)[i - SP_B01]);
            } else {
                sp2 += sp4(((const float4*)obj2)[i - SP_B12]);
            }
        }
    }
    __syncthreads();

    // ---- collision resolution: fully unrolled, branchless ----
    int mlpk = mypk;
    int lose = 0;
    #pragma unroll
    for (int j = 0; j < NBOX; j++) {
        int pj = spk[j];
        bool eq = (((pj ^ mypk) & ~31) == 0);    // same cell
        mlpk = (eq && pj < mlpk) ? pj : mlpk;     // min label among same-cell boxes
        lose |= (eq && j > box) ? 1 : 0;          // a later box overwrites this cell
    }
    int ml = mlpk & 31;
    bool winner = (lose == 0);

    // ---- group-of-4 combine (contiguous lanes, same warp) ----
    float m = v[0];
    #pragma unroll
    for (int i = 1; i < 8; i++) m = fmaxf(m, v[i]);
    m = fmaxf(m, __shfl_xor_sync(0xffffffffu, m, 1));
    m = fmaxf(m, __shfl_xor_sync(0xffffffffu, m, 2));

    float ssum = 0.0f, tgt = 0.0f;
    #pragma unroll
    for (int i = 0; i < 8; i++) {
        int c = cbase + i;
        ssum += __expf(v[i] - m);                 // padded entries -> exp(-huge)=0
        tgt = (c == ml) ? v[i] : tgt;
    }
    float bc = (part == 0) ? bx.x : (part == 1) ? bx.y : (part == 2) ? bx.z : bx.w;
    float d = fabsf(regv - bc);
    float sl = (d < 1.0f) ? 0.5f * d * d : d - 0.5f;

    ssum += __shfl_xor_sync(0xffffffffu, ssum, 1);
    ssum += __shfl_xor_sync(0xffffffffu, ssum, 2);
    tgt  += __shfl_xor_sync(0xffffffffu, tgt, 1);
    tgt  += __shfl_xor_sync(0xffffffffu, tgt, 2);
    sl   += __shfl_xor_sync(0xffffffffu, sl, 1);
    sl   += __shfl_xor_sync(0xffffffffu, sl, 2);

    float cls_l = 0.0f, reg_l = 0.0f, objp_l = 0.0f, np_l = 0.0f;
    if (winner) {
        if (part == 0) {
            np_l  = 1.0f;
            cls_l = m + __logf(ssum) - tgt;
            reg_l = fminf(sl * 0.25f, 10.0f);
        }
        if (part == 3) objp_l = objv;
    }
    __shared__ float res[4];
    blk_reduce4(cls_l, reg_l, objp_l, np_l, res);
    if (t == 0) __stcg(&g_blk_as[idx], make_float4(res[0], res[1], res[2], res[3]));

    __shared__ float rsp[4];
    blk_reduce4(sp0, sp1, sp2, 0.0f, rsp);
    if (t == 0) __stcg(&g_blk_sp[idx], make_float4(rsp[0], rsp[1], rsp[2], 0.0f));

    // ---- last arriving block: deterministic final reduce ----
    __shared__ bool amLast;
    if (t == 0) {
        __threadfence();   // order this block's partial stores before the ticket
        unsigned vv = atomicAdd(&g_done, 1u);
        amLast = (vv == (unsigned)(gridDim.x - 1));
        if (amLast) __threadfence();   // acquire: see all other blocks' partials
    }
    __syncthreads();
    if (!amLast) return;

    // softplus partials: one float4 per thread for t<48
    float4 p4 = make_float4(0.f, 0.f, 0.f, 0.f);
    float4 a4 = make_float4(0.f, 0.f, 0.f, 0.f);
    if (t < AS_BLOCKS) {
        p4 = __ldcg(&g_blk_sp[t]);
        a4 = __ldcg(&g_blk_as[t]);
    }
    __shared__ float spr[4];
    blk_reduce4(p4.x, p4.y, p4.z, 0.0f, spr);

    // assignment partials: 3 masked passes (one per scale)
    int myscale = t >> 4;
    __shared__ float asr[3][4];
    #pragma unroll
    for (int ss = 0; ss < 3; ss++) {
        bool on = (t < AS_BLOCKS) && (myscale == ss);
        __shared__ float tmp[4];
        blk_reduce4(on ? a4.x : 0.f, on ? a4.y : 0.f, on ? a4.z : 0.f, on ? a4.w : 0.f, tmp);
        if (t == 0) { asr[ss][0] = tmp[0]; asr[ss][1] = tmp[1]; asr[ss][2] = tmp[2]; asr[ss][3] = tmp[3]; }
    }

    if (t == 0) {
        float cls_tot = 0.0f, reg_tot = 0.0f, obj_tot = 0.0f;
        #pragma unroll
        for (int ss = 0; ss < 3; ss++) {
            float npos = fmaxf(asr[ss][3], 1.0f);
            int Wds = 80 >> ss;
            float Ms = (float)(NBATCH * Wds * Wds);
            cls_tot += asr[ss][0] / npos;               // CLS_W = 1
            reg_tot += asr[ss][1] / npos * 5.0f;        // REG_W = 5
            obj_tot += (spr[ss] - asr[ss][2]) / Ms;     // OBJ_W = 1
        }
        cls_tot *= (1.0f / 3.0f);
        reg_tot *= (1.0f / 3.0f);
        obj_tot *= (1.0f / 3.0f);
        out[0] = cls_tot + reg_tot + obj_tot;
        out[1] = cls_tot;
        out[2] = reg_tot;
        out[3] = obj_tot;
        g_done = 0;   // reset for next graph replay
    }
}

extern "C" void kernel_launch(void* const* d_in, const int* in_sizes, int n_in,
                              void* d_out, int out_size)
{
    const float *cls[3], *reg[3], *obj[3];
    if (in_sizes[1] == 409600) {   // dict order: cls0,reg0,obj0,cls1,...
        cls[0] = (const float*)d_in[0]; reg[0] = (const float*)d_in[1]; obj[0] = (const float*)d_in[2];
        cls[1] = (const float*)d_in[3]; reg[1] = (const float*)d_in[4]; obj[1] = (const float*)d_in[5];
        cls[2] = (const float*)d_in[6]; reg[2] = (const float*)d_in[7]; obj[2] = (const float*)d_in[8];
    } else {                        // signature order: cls0,cls1,cls2,reg0,...
        cls[0] = (const float*)d_in[0]; cls[1] = (const float*)d_in[1]; cls[2] = (const float*)d_in[2];
        reg[0] = (const float*)d_in[3]; reg[1] = (const float*)d_in[4]; reg[2] = (const float*)d_in[5];
        obj[0] = (const float*)d_in[6]; obj[1] = (const float*)d_in[7]; obj[2] = (const float*)d_in[8];
    }
    const float* boxes  = (const float*)d_in[9];
    const int*   labels = (const int*)d_in[10];
    float* out = (float*)d_out;

    detloss_kernel<<<AS_BLOCKS, TPB>>>(
        cls[0], cls[1], cls[2],
        reg[0], reg[1], reg[2],
        obj[0], obj[1], obj[2],
        boxes, labels, out);
}

// round 8
// speedup vs baseline: 1.0238x; 1.0208x over previous
#include <cuda_runtime.h>
#include <math.h>

#define TPB 256
#define NBATCH 16
#define NBOX 64
#define NCLS 30

// softplus blocks: each handles 512 float4 (2048 floats)
#define SP0_BLOCKS 50
#define SP1_BLOCKS 13
#define SP2_BLOCKS 4
#define SP_BLOCKS (SP0_BLOCKS + SP1_BLOCKS + SP2_BLOCKS)   // 67
#define AS_BLOCKS 48                                        // 3 scales * 16 batches
#define TOTAL_BLOCKS (SP_BLOCKS + AS_BLOCKS)                // 115

__device__ float  g_blk_sp[SP_BLOCKS];
__device__ float4 g_blk_as[AS_BLOCKS];     // {cls_sum, reg_sum, obj_pos_sum, npos}
__device__ unsigned int g_done = 0;

static __device__ __forceinline__ float softplus_f(float x) {
    return fmaxf(x, 0.0f) + __logf(1.0f + __expf(-fabsf(x)));
}

// block reduce; result valid on thread 0
static __device__ __forceinline__ float blk_reduce(float v) {
    __shared__ float sh[TPB / 32];
    __syncthreads();
    #pragma unroll
    for (int o = 16; o > 0; o >>= 1) v += __shfl_down_sync(0xffffffffu, v, o);
    int lane = threadIdx.x & 31, w = threadIdx.x >> 5;
    if (lane == 0) sh[w] = v;
    __syncthreads();
    v = (threadIdx.x < TPB / 32) ? sh[threadIdx.x] : 0.0f;
    if (w == 0) {
        #pragma unroll
        for (int o = TPB / 64; o > 0; o >>= 1) v += __shfl_down_sync(0xffffffffu, v, o);
    }
    return v;
}

// fused 4-value block reduce (2 barriers); results valid on thread 0 in r[0..3]
static __device__ __forceinline__ void blk_reduce4(float v0, float v1, float v2, float v3,
                                                   float* r) {
    __shared__ float sh[TPB / 32][4];
    __syncthreads();
    #pragma unroll
    for (int o = 16; o > 0; o >>= 1) {
        v0 += __shfl_xor_sync(0xffffffffu, v0, o);
        v1 += __shfl_xor_sync(0xffffffffu, v1, o);
        v2 += __shfl_xor_sync(0xffffffffu, v2, o);
        v3 += __shfl_xor_sync(0xffffffffu, v3, o);
    }
    int lane = threadIdx.x & 31, w = threadIdx.x >> 5;
    if (lane == 0) { sh[w][0] = v0; sh[w][1] = v1; sh[w][2] = v2; sh[w][3] = v3; }
    __syncthreads();
    if (threadIdx.x == 0) {
        float a = 0.f, b = 0.f, c = 0.f, d = 0.f;
        #pragma unroll
        for (int i = 0; i < TPB / 32; i++) {
            a += sh[i][0]; b += sh[i][1]; c += sh[i][2]; d += sh[i][3];
        }
        r[0] = a; r[1] = b; r[2] = c; r[3] = d;
    }
}

__global__ __launch_bounds__(TPB)
void detloss_kernel(const float* __restrict__ cls0, const float* __restrict__ cls1,
                    const float* __restrict__ cls2,
                    const float* __restrict__ reg0, const float* __restrict__ reg1,
                    const float* __restrict__ reg2,
                    const float* __restrict__ obj0, const float* __restrict__ obj1,
                    const float* __restrict__ obj2,
                    const float* __restrict__ boxes, const int* __restrict__ labels,
                    float* __restrict__ out)
{
    const float* clsp[3] = {cls0, cls1, cls2};
    const float* regp[3] = {reg0, reg1, reg2};
    const float* objp[3] = {obj0, obj1, obj2};

    int bid = blockIdx.x;
    int t = threadIdx.x;

    if (bid < SP_BLOCKS) {
        // ---- objectness softplus sum: 2 float4 per thread ----
        const float4* src;
        int base, lim;
        if (bid < SP0_BLOCKS) {
            src = (const float4*)obj0; base = bid * 512; lim = 25600;
        } else if (bid < SP0_BLOCKS + SP1_BLOCKS) {
            src = (const float4*)obj1; base = (bid - SP0_BLOCKS) * 512; lim = 6400;
        } else {
            src = (const float4*)obj2; base = (bid - SP0_BLOCKS - SP1_BLOCKS) * 512; lim = 1600;
        }
        int i0 = base + t, i1 = base + 256 + t;
        float acc = 0.0f;
        if (i0 < lim) {
            float4 v = src[i0];
            acc += softplus_f(v.x) + softplus_f(v.y) + softplus_f(v.z) + softplus_f(v.w);
        }
        if (i1 < lim) {
            float4 v = src[i1];
            acc += softplus_f(v.x) + softplus_f(v.y) + softplus_f(v.z) + softplus_f(v.w);
        }
        float tot = blk_reduce(acc);
        if (t == 0) __stcg(&g_blk_sp[bid], tot);
    } else {
        // ---- per (scale, batch): 4 threads per box ----
        int idx = bid - SP_BLOCKS;
        int s = idx >> 4;          // 0..2
        int b = idx & 15;          // 0..15
        int Wd = 80 >> s;          // 80, 40, 20
        int HW = Wd * Wd;

        int box  = t >> 2;         // 0..63
        int part = t & 3;          // 0..3

        __shared__ int spk[NBOX];  // packed (cell<<5)|label

        // box coords + cell (all 4 parts compute identically; broadcast loads)
        const float4 bx = ((const float4*)boxes)[b * NBOX + box];
        int gx = (int)(bx.x * (float)Wd);
        int gy = (int)(bx.y * (float)Wd);
        gx = max(0, min(gx, Wd - 1));
        gy = max(0, min(gy, Wd - 1));
        int cell = gy * Wd + gx;
        int lab  = labels[b * NBOX + box];
        int mypk = (cell << 5) | lab;
        if (part == 0) spk[box] = mypk;

        // ---- speculative gathers (issued before the barrier; scattered) ----
        // classes: part p covers [8p, 8p+8) (part 3: 6 real + 2 padded)
        int cbase = part * 8;
        const float* cp = clsp[s] + (size_t)b * NCLS * HW + cell;
        float v[8];
        #pragma unroll
        for (int i = 0; i < 8; i++) {
            int c = cbase + i;
            int cc = min(c, NCLS - 1);
            float val = __ldg(&cp[(size_t)cc * HW]);
            v[i] = (c < NCLS) ? val : -1e30f;
        }
        // reg: part p loads coordinate p
        float regv = __ldg(&regp[s][(size_t)b * 4 * HW + (size_t)part * HW + cell]);
        // obj: part 3 loads it
        float objv = (part == 3) ? __ldg(&objp[s][(size_t)b * HW + cell]) : 0.0f;
        __syncthreads();

        // ---- collision resolution: fully unrolled, branchless ----
        int mlpk = mypk;
        int lose = 0;
        #pragma unroll
        for (int j = 0; j < NBOX; j++) {
            int pj = spk[j];
            bool eq = (((pj ^ mypk) & ~31) == 0);   // same cell
            mlpk = (eq && pj < mlpk) ? pj : mlpk;    // min label among same-cell boxes
            lose |= (eq && j > box) ? 1 : 0;         // a later box overwrites this cell
        }
        int ml = mlpk & 31;
        bool winner = (lose == 0);

        // ---- group-of-4 combine (contiguous lanes, same warp) ----
        float m = v[0];
        #pragma unroll
        for (int i = 1; i < 8; i++) m = fmaxf(m, v[i]);
        m = fmaxf(m, __shfl_xor_sync(0xffffffffu, m, 1));
        m = fmaxf(m, __shfl_xor_sync(0xffffffffu, m, 2));

        float ssum = 0.0f, tgt = 0.0f;
        #pragma unroll
        for (int i = 0; i < 8; i++) {
            int c = cbase + i;
            ssum += __expf(v[i] - m);                // padded entries -> exp(-huge)=0
            tgt = (c == ml) ? v[i] : tgt;
        }
        float bc = (part == 0) ? bx.x : (part == 1) ? bx.y : (part == 2) ? bx.z : bx.w;
        float d = fabsf(regv - bc);
        float sl = (d < 1.0f) ? 0.5f * d * d : d - 0.5f;

        ssum += __shfl_xor_sync(0xffffffffu, ssum, 1);
        ssum += __shfl_xor_sync(0xffffffffu, ssum, 2);
        tgt  += __shfl_xor_sync(0xffffffffu, tgt, 1);
        tgt  += __shfl_xor_sync(0xffffffffu, tgt, 2);
        sl   += __shfl_xor_sync(0xffffffffu, sl, 1);
        sl   += __shfl_xor_sync(0xffffffffu, sl, 2);

        float cls_l = 0.0f, reg_l = 0.0f, objp_l = 0.0f, np_l = 0.0f;
        if (winner) {
            if (part == 0) {
                np_l  = 1.0f;
                cls_l = m + __logf(ssum) - tgt;
                reg_l = fminf(sl * 0.25f, 10.0f);
            }
            if (part == 3) objp_l = objv;
        }
        __shared__ float res[4];
        blk_reduce4(cls_l, reg_l, objp_l, np_l, res);
        if (t == 0) {
            float4 o4 = make_float4(res[0], res[1], res[2], res[3]);
            __stcg(&g_blk_as[idx], o4);
        }
    }

    // ---- last arriving block: deterministic final reduce ----
    __shared__ bool amLast;
    if (t == 0) {
        __threadfence();   // order this block's partial store before the ticket
        unsigned vv = atomicAdd(&g_done, 1u);
        amLast = (vv == (unsigned)(gridDim.x - 1));
        if (amLast) __threadfence();   // acquire: see all other blocks' partials
    }
    __syncthreads();
    if (!amLast) return;

    // ---- fast tail: single warp-parallel pass, one barrier ----
    int lane = t & 31, w = t >> 5;
    __shared__ float fin[6][4];   // [0..2]: asgn per scale {cls,reg,objp,npos}; [3..5]: sp sums {s0,s1,s2,-}

    if (w < 3) {
        // warp w reduces the 16 assignment partials of scale w
        float4 a4 = make_float4(0.f, 0.f, 0.f, 0.f);
        if (lane < NBATCH) a4 = __ldcg(&g_blk_as[w * NBATCH + lane]);
        #pragma unroll
        for (int o = 8; o > 0; o >>= 1) {
            a4.x += __shfl_xor_sync(0xffffffffu, a4.x, o);
            a4.y += __shfl_xor_sync(0xffffffffu, a4.y, o);
            a4.z += __shfl_xor_sync(0xffffffffu, a4.z, o);
            a4.w += __shfl_xor_sync(0xffffffffu, a4.w, o);
        }
        if (lane == 0) { fin[w][0] = a4.x; fin[w][1] = a4.y; fin[w][2] = a4.z; fin[w][3] = a4.w; }
    } else if (w < 6) {
        // warps 3..5 reduce the 67 softplus partials, masked into 3 per-scale sums
        int i = (w - 3) * 32 + lane;
        float pv = (i < SP_BLOCKS) ? __ldcg(&g_blk_sp[i]) : 0.0f;
        float l0 = (i < SP0_BLOCKS) ? pv : 0.0f;
        float l1 = (i >= SP0_BLOCKS && i < SP0_BLOCKS + SP1_BLOCKS) ? pv : 0.0f;
        float l2 = (i >= SP0_BLOCKS + SP1_BLOCKS && i < SP_BLOCKS) ? pv : 0.0f;
        #pragma unroll
        for (int o = 16; o > 0; o >>= 1) {
            l0 += __shfl_xor_sync(0xffffffffu, l0, o);
            l1 += __shfl_xor_sync(0xffffffffu, l1, o);
            l2 += __shfl_xor_sync(0xffffffffu, l2, o);
        }
        if (lane == 0) { fin[w][0] = l0; fin[w][1] = l1; fin[w][2] = l2; fin[w][3] = 0.0f; }
    }
    __syncthreads();

    if (t == 0) {
        float cls_tot = 0.0f, reg_tot = 0.0f, obj_tot = 0.0f;
        #pragma unroll
        for (int s = 0; s < 3; s++) {
            float sp_s = fin[3][s] + fin[4][s] + fin[5][s];
            float npos = fmaxf(fin[s][3], 1.0f);
            int Wd = 80 >> s;
            float Ms = (float)(NBATCH * Wd * Wd);
            cls_tot += fin[s][0] / npos;               // CLS_W = 1
            reg_tot += fin[s][1] / npos * 5.0f;        // REG_W = 5
            obj_tot += (sp_s - fin[s][2]) / Ms;        // OBJ_W = 1
        }
        cls_tot *= (1.0f / 3.0f);
        reg_tot *= (1.0f / 3.0f);
        obj_tot *= (1.0f / 3.0f);
        out[0] = cls_tot + reg_tot + obj_tot;
        out[1] = cls_tot;
        out[2] = reg_tot;
        out[3] = obj_tot;
        g_done = 0;   // reset for next graph replay
    }
}

extern "C" void kernel_launch(void* const* d_in, const int* in_sizes, int n_in,
                              void* d_out, int out_size)
{
    const float *cls[3], *reg[3], *obj[3];
    if (in_sizes[1] == 409600) {   // dict order: cls0,reg0,obj0,cls1,...
        cls[0] = (const float*)d_in[0]; reg[0] = (const float*)d_in[1]; obj[0] = (const float*)d_in[2];
        cls[1] = (const float*)d_in[3]; reg[1] = (const float*)d_in[4]; obj[1] = (const float*)d_in[5];
        cls[2] = (const float*)d_in[6]; reg[2] = (const float*)d_in[7]; obj[2] = (const float*)d_in[8];
    } else {                        // signature order: cls0,cls1,cls2,reg0,...
        cls[0] = (const float*)d_in[0]; cls[1] = (const float*)d_in[1]; cls[2] = (const float*)d_in[2];
        reg[0] = (const float*)d_in[3]; reg[1] = (const float*)d_in[4]; reg[2] = (const float*)d_in[5];
        obj[0] = (const float*)d_in[6]; obj[1] = (const float*)d_in[7]; obj[2] = (const float*)d_in[8];
    }
    const float* boxes  = (const float*)d_in[9];
    const int*   labels = (const int*)d_in[10];
    float* out = (float*)d_out;

    detloss_kernel<<<TOTAL_BLOCKS, TPB>>>(
        cls[0], cls[1], cls[2],
        reg[0], reg[1], reg[2],
        obj[0], obj[1], obj[2],
        boxes, labels, out);
}